// round 2
// baseline (speedup 1.0000x reference)
#include <cuda_runtime.h>

#define NN 50000      // nodes per table (N_U == N_I)
#define DD 64
#define HH 128
#define EE 500000
#define ZSZ (NN*DD)   // floats per z-plane

typedef unsigned long long ull;

// ---------------------------------------------------------------- scratch
__device__ float g_z[(size_t)8*ZSZ];   // 0-3: GAT planes, 4-7: GC planes
__device__ int   g_cur[8*NN];          // counts, then fill cursors
__device__ int   g_rp[8*NN];           // inclusive row offsets per graph
__device__ int   g_odeg[4*NN];         // GC out-degrees
__device__ int   g_bsum[8*256];        // scan block sums
__device__ int   g_csrc[(size_t)8*EE]; // CSR: src index per edge slot
__device__ float g_el[4*NN];
__device__ float g_er[4*NN];
__device__ float g_no[4*NN];           // GC out-norm rsqrt
__device__ float g_wsum[8];
__device__ float g_beta[8];

struct P8  { const int* s[8]; const int* d[8]; };
struct F4  { const float* f[4]; };
struct LerP{ const float* fs[4]; const float* fd[4]; };
struct SaP { const float* W1[4]; const float* b1[4]; const float* w2[4]; };

// ---------------------------------------------------------------- f32x2 utils
__device__ __forceinline__ ull pack2(float a, float b) {
    ull r; asm("mov.b64 %0, {%1,%2};" : "=l"(r) : "f"(a), "f"(b)); return r;
}
__device__ __forceinline__ void unpack2(ull v, float& a, float& b) {
    asm("mov.b64 {%0,%1}, %2;" : "=f"(a), "=f"(b) : "l"(v));
}
__device__ __forceinline__ ull ffma2(ull a, ull b, ull c) {
    ull d; asm("fma.rn.f32x2 %0, %1, %2, %3;" : "=l"(d) : "l"(a), "l"(b), "l"(c));
    return d;
}
__device__ __forceinline__ float tanha(float x) {
    float r; asm("tanh.approx.f32 %0, %1;" : "=f"(r) : "f"(x)); return r;
}
__device__ __forceinline__ float elu(float x) { return x > 0.f ? x : expm1f(x); }

// ---------------------------------------------------------------- zero
__global__ void zero_k() {
    int t = blockIdx.x * blockDim.x + threadIdx.x;
    if (t < 8*NN) g_cur[t] = 0;
    if (t < 4*NN) g_odeg[t] = 0;
    if (t < 8)    g_wsum[t] = 0.f;
}

// ---------------------------------------------------------------- CSR build
__global__ void count_k(P8 P) {
    int e = blockIdx.x * blockDim.x + threadIdx.x;
    int g = blockIdx.y;
    if (e >= EE) return;
    int d = __ldg(P.d[g] + e);
    atomicAdd(g_cur + g*NN + d, 1);
    if (g >= 4) {
        int s = __ldg(P.s[g] + e);
        atomicAdd(g_odeg + (g-4)*NN + s, 1);
    }
}

__global__ void scan1_k() {
    __shared__ int sh[256];
    int g = blockIdx.y, t = threadIdx.x;
    int p = blockIdx.x * 256 + t;
    int v = (p < NN) ? g_cur[g*NN + p] : 0;
    sh[t] = v; __syncthreads();
    #pragma unroll
    for (int off = 1; off < 256; off <<= 1) {
        int x = (t >= off) ? sh[t-off] : 0;
        __syncthreads();
        sh[t] += x;
        __syncthreads();
    }
    if (p < NN) g_rp[g*NN + p] = sh[t];
    if (t == 255) g_bsum[g*256 + blockIdx.x] = sh[255];
}

__global__ void scan2_k() {
    __shared__ int sh[256];
    int g = blockIdx.x, t = threadIdx.x;
    int v = (t < 196) ? g_bsum[g*256 + t] : 0;
    sh[t] = v; __syncthreads();
    #pragma unroll
    for (int off = 1; off < 256; off <<= 1) {
        int x = (t >= off) ? sh[t-off] : 0;
        __syncthreads();
        sh[t] += x;
        __syncthreads();
    }
    if (t < 196) g_bsum[g*256 + t] = sh[t] - v;   // exclusive
}

__global__ void scan3_k() {
    int g = blockIdx.y, t = threadIdx.x;
    int p = blockIdx.x * 256 + t;
    if (p >= NN) return;
    int add = g_bsum[g*256 + blockIdx.x];
    int cnt = g_cur[g*NN + p];
    int incl = g_rp[g*NN + p] + add;
    g_rp[g*NN + p] = incl;
    g_cur[g*NN + p] = incl - cnt;   // fill cursor = exclusive start
    if (g >= 4)
        g_no[(g-4)*NN + p] = rsqrtf((float)max(g_odeg[(g-4)*NN + p], 1));
}

__global__ void fill_k(P8 P) {
    int e = blockIdx.x * blockDim.x + threadIdx.x;
    int g = blockIdx.y;
    if (e >= EE) return;
    int d = __ldg(P.d[g] + e);
    int pos = atomicAdd(g_cur + g*NN + d, 1);
    g_csrc[(size_t)g*EE + pos] = __ldg(P.s[g] + e);
}

// ---------------------------------------------------------------- GAT el/er
__global__ void ler_k(LerP P, const float* __restrict__ attn_l,
                      const float* __restrict__ attn_r) {
    int g = blockIdx.y;
    int w = (blockIdx.x * blockDim.x + threadIdx.x) >> 5;
    int lane = threadIdx.x & 31;
    const float* f; const float* a; float* out;
    if (w < NN) {
        f = P.fs[g] + (size_t)w * DD; a = attn_l + g*DD; out = g_el + g*NN + w;
    } else {
        int n = w - NN;
        f = P.fd[g] + (size_t)n * DD; a = attn_r + g*DD; out = g_er + g*NN + n;
    }
    float s = f[lane]*a[lane] + f[lane+32]*a[lane+32];
    #pragma unroll
    for (int o = 16; o; o >>= 1) s += __shfl_down_sync(0xffffffffu, s, o);
    if (lane == 0) *out = s;
}

// ---------------------------------------------------------------- GAT gather
// Half-warp (16 lanes) per dst node. float4 per lane covers 64 dims.
__global__ void gat_gather_k(F4 P) {
    int g = blockIdx.y;
    int hw = threadIdx.x >> 4, l = threadIdx.x & 15;
    unsigned hm = 0xFFFFu << (threadIdx.x & 16);
    int node = blockIdx.x * 16 + hw;

    const int* rp = g_rp + g*NN;
    int end = __ldg(rp + node);
    int start = node ? __ldg(rp + node - 1) : 0;
    const float* el = g_el + g*NN;
    float er = g_er[g*NN + node];
    const int* cs = g_csrc + (size_t)g*EE;
    const float4* F = (const float4*)P.f[g];

    float4 acc = make_float4(0.f,0.f,0.f,0.f);
    float dsum = 0.f;

    for (int base = start; base < end; base += 16) {
        int m = end - base; if (m > 16) m = 16;
        int si = 0; float ex = 0.f;
        if (l < m) {
            si = __ldg(cs + base + l);
            float e = el[si] + er;
            e = e > 0.f ? e : 0.01f * e;
            ex = __expf(e);
            dsum += ex;
        }
        int   sj = __shfl_sync(hm, si, 0, 16);
        float wj = __shfl_sync(hm, ex, 0, 16);
        float4 f = __ldg(F + (size_t)sj*16 + l);
        for (int j = 1; j < m; j++) {
            int   s2 = __shfl_sync(hm, si, j, 16);
            float w2 = __shfl_sync(hm, ex, j, 16);
            float4 f2 = __ldg(F + (size_t)s2*16 + l);
            acc.x += wj*f.x; acc.y += wj*f.y; acc.z += wj*f.z; acc.w += wj*f.w;
            wj = w2; f = f2;
        }
        acc.x += wj*f.x; acc.y += wj*f.y; acc.z += wj*f.z; acc.w += wj*f.w;
    }
    #pragma unroll
    for (int o = 8; o; o >>= 1) dsum += __shfl_xor_sync(hm, dsum, o, 16);
    float inv = dsum > 0.f ? 1.f / dsum : 0.f;
    float4 r;
    r.x = elu(acc.x * inv); r.y = elu(acc.y * inv);
    r.z = elu(acc.z * inv); r.w = elu(acc.w * inv);
    ((float4*)(g_z + (size_t)g*ZSZ))[(size_t)node*16 + l] = r;
}

// ------------------------------------------- GC gather + fused 64x64 GEMM+ELU
__global__ void gc_gather_gemm_k(F4 P, const float* __restrict__ W_gc,
                                 const float* __restrict__ b_gc) {
    __shared__ float Wsh[DD*DD];
    __shared__ float bsh[DD];
    int g = blockIdx.y, t = threadIdx.x;
    const float* W = W_gc + g*DD*DD;
    for (int i = t; i < DD*DD; i += 256) Wsh[i] = W[i];
    if (t < DD) bsh[t] = b_gc[g*DD + t];
    __syncthreads();

    int hw = t >> 4, l = t & 15;
    unsigned hm = 0xFFFFu << (t & 16);
    int node = blockIdx.x * 16 + hw;

    const int* rp = g_rp + (4+g)*NN;
    int end = __ldg(rp + node);
    int start = node ? __ldg(rp + node - 1) : 0;
    const float* no = g_no + g*NN;
    const int* cs = g_csrc + (size_t)(4+g)*EE;
    const float4* F = (const float4*)P.f[g];

    float4 acc = make_float4(0.f,0.f,0.f,0.f);
    for (int base = start; base < end; base += 16) {
        int m = end - base; if (m > 16) m = 16;
        int si = 0; float wv = 0.f;
        if (l < m) { si = __ldg(cs + base + l); wv = __ldg(no + si); }
        int   sj = __shfl_sync(hm, si, 0, 16);
        float wj = __shfl_sync(hm, wv, 0, 16);
        float4 f = __ldg(F + (size_t)sj*16 + l);
        for (int j = 1; j < m; j++) {
            int   s2 = __shfl_sync(hm, si, j, 16);
            float w2 = __shfl_sync(hm, wv, j, 16);
            float4 f2 = __ldg(F + (size_t)s2*16 + l);
            acc.x += wj*f.x; acc.y += wj*f.y; acc.z += wj*f.z; acc.w += wj*f.w;
            wj = w2; f = f2;
        }
        acc.x += wj*f.x; acc.y += wj*f.y; acc.z += wj*f.z; acc.w += wj*f.w;
    }
    int deg = end - start;
    float ni = rsqrtf((float)(deg > 0 ? deg : 1));
    acc.x *= ni; acc.y *= ni; acc.z *= ni; acc.w *= ni;

    // GEMV within half-warp: out dims 4l..4l+3
    float4 o = ((const float4*)bsh)[l];
    #pragma unroll
    for (int d = 0; d < DD; d++) {
        float v;
        switch (d & 3) {
            case 0: v = __shfl_sync(hm, acc.x, d >> 2, 16); break;
            case 1: v = __shfl_sync(hm, acc.y, d >> 2, 16); break;
            case 2: v = __shfl_sync(hm, acc.z, d >> 2, 16); break;
            default:v = __shfl_sync(hm, acc.w, d >> 2, 16); break;
        }
        float4 w4 = ((const float4*)Wsh)[d*16 + l];
        o.x += v*w4.x; o.y += v*w4.y; o.z += v*w4.z; o.w += v*w4.w;
    }
    float4 r;
    r.x = elu(o.x); r.y = elu(o.y); r.z = elu(o.z); r.w = elu(o.w);
    ((float4*)(g_z + (size_t)(4+g)*ZSZ))[(size_t)node*16 + l] = r;
}

// ---------------------------------------------------- semantic attention score
// 64 nodes per block; 4 threads per node, 32 h each; FFMA2 inner loop.
#define ZSTRIDE 68
__global__ void __launch_bounds__(256) sa_score_k(SaP P) {
    extern __shared__ float sm[];
    float* W1sh = sm;                      // 8192
    float* zA   = sm + 8192;               // 64*68
    float* zB   = zA + 64*ZSTRIDE;
    float* b1sh = zB + 64*ZSTRIDE;         // 128
    float* w2sh = b1sh + 128;              // 128
    float* red  = w2sh + 128;              // 4

    int gg = blockIdx.y, t = threadIdx.x;
    for (int i = t; i < DD*HH; i += 256) W1sh[i] = P.W1[gg][i];
    if (t < HH) { b1sh[t] = P.b1[gg][t]; w2sh[t] = P.w2[gg][t]; }
    if (t < 2) red[t] = 0.f;

    int nodeBase = blockIdx.x * 64;
    const float4* p0 = (const float4*)(g_z + (size_t)(2*gg)*ZSZ);
    const float4* p1 = p0 + ZSZ/4;
    for (int idx = t; idx < 1024; idx += 256) {
        int n = idx >> 4, v = idx & 15;
        int gn = nodeBase + n;
        float4 a = make_float4(0.f,0.f,0.f,0.f), b = a;
        if (gn < NN) { a = __ldg(p0 + (size_t)gn*16 + v); b = __ldg(p1 + (size_t)gn*16 + v); }
        ((float4*)(zA + n*ZSTRIDE))[v] = a;
        ((float4*)(zB + n*ZSTRIDE))[v] = b;
    }
    __syncthreads();

    int nb = t >> 2;             // node within block
    int hq = (t & 3) * 32;       // h chunk
    ull acc0[16], acc1[16];
    const ull* bp = (const ull*)(b1sh + hq);
    #pragma unroll
    for (int i = 0; i < 16; i++) { acc0[i] = bp[i]; acc1[i] = bp[i]; }

    const float* za = zA + nb*ZSTRIDE;
    const float* zb = zB + nb*ZSTRIDE;
    for (int d = 0; d < DD; d++) {
        ull va = pack2(za[d], za[d]);
        ull vb = pack2(zb[d], zb[d]);
        const ulonglong2* wp = (const ulonglong2*)(W1sh + d*HH + hq);
        #pragma unroll
        for (int i = 0; i < 8; i++) {
            ulonglong2 w = wp[i];
            acc0[2*i]   = ffma2(va, w.x, acc0[2*i]);
            acc0[2*i+1] = ffma2(va, w.y, acc0[2*i+1]);
            acc1[2*i]   = ffma2(vb, w.x, acc1[2*i]);
            acc1[2*i+1] = ffma2(vb, w.y, acc1[2*i+1]);
        }
    }

    float part0 = 0.f, part1 = 0.f;
    if (nodeBase + nb < NN) {
        #pragma unroll
        for (int i = 0; i < 16; i++) {
            float lo, hi;
            float wa = w2sh[hq + 2*i], wb = w2sh[hq + 2*i + 1];
            unpack2(acc0[i], lo, hi);
            part0 += tanha(lo)*wa + tanha(hi)*wb;
            unpack2(acc1[i], lo, hi);
            part1 += tanha(lo)*wa + tanha(hi)*wb;
        }
    }
    #pragma unroll
    for (int o = 16; o; o >>= 1) {
        part0 += __shfl_down_sync(0xffffffffu, part0, o);
        part1 += __shfl_down_sync(0xffffffffu, part1, o);
    }
    if ((t & 31) == 0) { atomicAdd(&red[0], part0); atomicAdd(&red[1], part1); }
    __syncthreads();
    if (t == 0) {
        atomicAdd(g_wsum + 2*gg,     red[0]);
        atomicAdd(g_wsum + 2*gg + 1, red[1]);
    }
}

// ---------------------------------------------------------------- beta
__global__ void beta_k() {
    #pragma unroll
    for (int g = 0; g < 4; g++) {
        float w0 = g_wsum[2*g]   * (1.0f/NN);
        float w1 = g_wsum[2*g+1] * (1.0f/NN);
        float m = fmaxf(w0, w1);
        float e0 = __expf(w0-m), e1 = __expf(w1-m);
        float inv = 1.f/(e0+e1);
        g_beta[2*g] = e0*inv; g_beta[2*g+1] = e1*inv;
    }
}

// ---------------------------------------------------------------- combine
__global__ void combine_k(float* __restrict__ out) {
    int t = blockIdx.x * blockDim.x + threadIdx.x;
    const int NT4 = 2*NN*16;
    if (t >= NT4) return;
    const float4* Z = (const float4*)g_z;
    const size_t Pp = ZSZ/4;
    float4 r;
    if (t < NN*16) {
        float b0=g_beta[0], b1=g_beta[1], b4=g_beta[4], b5=g_beta[5];
        float4 x0=Z[t], x1=Z[Pp+t], x4=Z[4*Pp+t], x5=Z[5*Pp+t];
        r.x = b0*x0.x+b1*x1.x+b4*x4.x+b5*x5.x;
        r.y = b0*x0.y+b1*x1.y+b4*x4.y+b5*x5.y;
        r.z = b0*x0.z+b1*x1.z+b4*x4.z+b5*x5.z;
        r.w = b0*x0.w+b1*x1.w+b4*x4.w+b5*x5.w;
    } else {
        size_t u = t - NN*16;
        float b2=g_beta[2], b3=g_beta[3], b6=g_beta[6], b7=g_beta[7];
        float4 x2=Z[2*Pp+u], x3=Z[3*Pp+u], x6=Z[6*Pp+u], x7=Z[7*Pp+u];
        r.x = b2*x2.x+b3*x3.x+b6*x6.x+b7*x7.x;
        r.y = b2*x2.y+b3*x3.y+b6*x6.y+b7*x7.y;
        r.z = b2*x2.z+b3*x3.z+b6*x6.z+b7*x7.z;
        r.w = b2*x2.w+b3*x3.w+b6*x6.w+b7*x7.w;
    }
    ((float4*)out)[t] = r;
}

// ============================================================== host launcher
extern "C" void kernel_launch(void* const* d_in, const int* in_sizes, int n_in,
                              void* d_out, int out_size) {
    const float* feat_user = (const float*)d_in[0];
    const float* feat_item = (const float*)d_in[1];
    const float* attn_l    = (const float*)d_in[2];
    const float* attn_r    = (const float*)d_in[3];
    const float* W_gc      = (const float*)d_in[4];
    const float* b_gc      = (const float*)d_in[5];
    const float* sa_rel_W1 = (const float*)d_in[6];
    const float* sa_rel_b1 = (const float*)d_in[7];
    const float* sa_rel_w2 = (const float*)d_in[8];
    const float* sa_u_W1   = (const float*)d_in[9];
    const float* sa_u_b1   = (const float*)d_in[10];
    const float* sa_u_w2   = (const float*)d_in[11];
    const float* sa_i_W1   = (const float*)d_in[12];
    const float* sa_i_b1   = (const float*)d_in[13];
    const float* sa_i_w2   = (const float*)d_in[14];
    const int* rel_u_src   = (const int*)d_in[15];
    const int* rel_u_dst   = (const int*)d_in[16];
    const int* rel_i_src   = (const int*)d_in[17];
    const int* rel_i_dst   = (const int*)d_in[18];
    const int* mp_u_src    = (const int*)d_in[19];
    const int* mp_u_dst    = (const int*)d_in[20];
    const int* mp_i_src    = (const int*)d_in[21];
    const int* mp_i_dst    = (const int*)d_in[22];
    float* out = (float*)d_out;

    P8 P;
    P.s[0]=rel_u_src;    P.d[0]=rel_u_dst;
    P.s[1]=rel_u_src+EE; P.d[1]=rel_u_dst+EE;
    P.s[2]=rel_i_src;    P.d[2]=rel_i_dst;
    P.s[3]=rel_i_src+EE; P.d[3]=rel_i_dst+EE;
    P.s[4]=mp_u_src;     P.d[4]=mp_u_dst;
    P.s[5]=mp_u_src+EE;  P.d[5]=mp_u_dst+EE;
    P.s[6]=mp_i_src;     P.d[6]=mp_i_dst;
    P.s[7]=mp_i_src+EE;  P.d[7]=mp_i_dst+EE;

    F4 Fg; Fg.f[0]=feat_item; Fg.f[1]=feat_item; Fg.f[2]=feat_user; Fg.f[3]=feat_user;
    F4 Fc; Fc.f[0]=feat_user; Fc.f[1]=feat_user; Fc.f[2]=feat_item; Fc.f[3]=feat_item;
    LerP L;
    L.fs[0]=feat_item; L.fd[0]=feat_user;
    L.fs[1]=feat_item; L.fd[1]=feat_user;
    L.fs[2]=feat_user; L.fd[2]=feat_item;
    L.fs[3]=feat_user; L.fd[3]=feat_item;
    SaP S;
    S.W1[0]=sa_rel_W1; S.b1[0]=sa_rel_b1; S.w2[0]=sa_rel_w2;
    S.W1[1]=sa_rel_W1; S.b1[1]=sa_rel_b1; S.w2[1]=sa_rel_w2;
    S.W1[2]=sa_u_W1;   S.b1[2]=sa_u_b1;   S.w2[2]=sa_u_w2;
    S.W1[3]=sa_i_W1;   S.b1[3]=sa_i_b1;   S.w2[3]=sa_i_w2;

    const int TB = 256;
    const int EDGE_BLKS = (EE + TB - 1) / TB;   // 1954
    const int NODE_BLKS = (NN + TB - 1) / TB;   // 196

    zero_k<<<(8*NN + TB - 1) / TB, TB>>>();
    count_k<<<dim3(EDGE_BLKS, 8), TB>>>(P);
    scan1_k<<<dim3(NODE_BLKS, 8), TB>>>();
    scan2_k<<<8, TB>>>();
    scan3_k<<<dim3(NODE_BLKS, 8), TB>>>();
    fill_k<<<dim3(EDGE_BLKS, 8), TB>>>(P);

    ler_k<<<dim3(2*NN*32/TB, 4), TB>>>(L, attn_l, attn_r);
    gat_gather_k<<<dim3(NN/16, 4), TB>>>(Fg);
    gc_gather_gemm_k<<<dim3(NN/16, 4), TB>>>(Fc, W_gc, b_gc);

    int sa_smem = (DD*HH + 2*64*ZSTRIDE + HH + HH + 4) * sizeof(float);
    cudaFuncSetAttribute(sa_score_k, cudaFuncAttributeMaxDynamicSharedMemorySize, sa_smem);
    sa_score_k<<<dim3((NN + 63)/64, 4), TB, sa_smem>>>(S);

    beta_k<<<1, 1>>>();
    combine_k<<<(2*NN*16 + TB - 1) / TB, TB>>>(out);
}